// round 12
// baseline (speedup 1.0000x reference)
#include <cuda_runtime.h>
#include <cuda_bf16.h>
#include <cuda_fp16.h>
#include <cstdint>

// ---------------------------------------------------------------------------
// CoAttention R11: online-softmax flash attention (register-resident P,
// no Ps smem buffer) + R9 fp16 GEMMs.
// ---------------------------------------------------------------------------

#define BB    8
#define NS    512
#define DM    512
#define NHEAD 8
#define DHH   64
#define DFF   2048
#define NLAY  4
#define LN_EPS 1e-5f

// ------------------------------- scratch -----------------------------------
__device__ float g_v  [BB*NS*DM];
__device__ float g_q  [BB*NS*DM];
__device__ float g_qkv[3*BB*NS*DM];
__device__ float g_sc [BB*NS*NS];
__device__ float g_ao [BB*NS*DM];
__device__ float g_tmp[BB*NS*DM];
__device__ float g_va [BB*NS*DM];
__device__ float g_qa [BB*NS*DM];
__device__ float g_vq [BB*NS*DM];
__device__ float g_qv [BB*NS*DM];
__device__ float g_ffn[BB*NS*DFF];

// ------------------------------- helpers -----------------------------------

__device__ __forceinline__ unsigned f2h2(float a, float b) {
    __half2 h = __floats2half2_rn(a, b);
    return *reinterpret_cast<unsigned*>(&h);
}

__device__ __forceinline__ void mma16816(float* c, const unsigned* a, const unsigned* b) {
    asm volatile(
        "mma.sync.aligned.m16n8k16.row.col.f32.f16.f16.f32 "
        "{%0,%1,%2,%3}, {%4,%5,%6,%7}, {%8,%9}, {%0,%1,%2,%3};\n"
        : "+f"(c[0]), "+f"(c[1]), "+f"(c[2]), "+f"(c[3])
        : "r"(a[0]), "r"(a[1]), "r"(a[2]), "r"(a[3]), "r"(b[0]), "r"(b[1]));
}

#define LDSM4(r0, r1, r2, r3, addr) \
    asm volatile("ldmatrix.sync.aligned.m8n8.x4.shared.b16 {%0,%1,%2,%3}, [%4];" \
        : "=r"(r0), "=r"(r1), "=r"(r2), "=r"(r3) : "r"(addr))

// GEMM smem strides (halves)
#define SH 40
#define ROWB 80
#define A2BUF (64  * ROWB)
#define B2BUF (128 * ROWB)

// flash-attention strides (bytes)
#define FA_KSTRB 144    // Q/K row stride (72 halves)
#define FA_VSTRB 272    // Vt row stride (136 halves)

// ------------------------------- kernels -----------------------------------

__global__ void copy_k(const float* __restrict__ src, float* __restrict__ dst, int n) {
    int i = blockIdx.x * blockDim.x + threadIdx.x;
    if (i < n) dst[i] = src[i];
}

// ======== NN GEMM fp16: block 64x128, BK=32, 128 thr, warp 32x64 ===========
__global__ __launch_bounds__(128) void mma_nn2h(
    const float* __restrict__ A, const float* __restrict__ B,
    const float* __restrict__ bias, float* __restrict__ C,
    int K, int lda, int ldb, int ldc,
    int zdiv, long long sA1, long long sA2, long long sB1, long long sB2,
    long long sC1, long long sC2, long long sBias, int relu)
{
    int z = blockIdx.z;
    int z1 = z / zdiv, z2 = z - z1 * zdiv;
    A += z1 * sA1 + (long long)z2 * sA2;
    B += z1 * sB1 + (long long)z2 * sB2;
    C += z1 * sC1 + (long long)z2 * sC2;
    if (bias) bias += (long long)z * sBias;

    __shared__ __align__(16) __half As[2][64][SH];
    __shared__ __align__(16) __half Bs[2][128][SH];

    const int tid = threadIdx.x;
    const int wid = tid >> 5, lane = tid & 31;
    const int wm = (wid >> 1) * 32, wn = (wid & 1) * 64;
    const int g = lane >> 2, t4 = lane & 3;
    const int row0 = blockIdx.y * 64, col0 = blockIdx.x * 128;

    const int a_r = tid >> 1, a_kh = (tid & 1) * 16;
    const float* Aptr = A + (long long)(row0 + a_r) * lda + a_kh;
    const float* Bptr = B + col0 + tid;

    const int lr = lane & 7, sel = lane >> 3;
    unsigned as0 = (unsigned)__cvta_generic_to_shared(&As[0][0][0]);
    unsigned bs0 = (unsigned)__cvta_generic_to_shared(&Bs[0][0][0]);
    unsigned aaddr = as0 + (unsigned)((wm + (sel & 1) * 8 + lr) * ROWB + (sel >> 1) * 16);
    unsigned baddr[4];
    #pragma unroll
    for (int j = 0; j < 4; j++)
        baddr[j] = bs0 + (unsigned)((wn + j * 16 + (sel >> 1) * 8 + lr) * ROWB + (sel & 1) * 16);

    float acc[2][8][4];
    #pragma unroll
    for (int mi = 0; mi < 2; mi++)
        #pragma unroll
        for (int ni = 0; ni < 8; ni++)
            #pragma unroll
            for (int r = 0; r < 4; r++) acc[mi][ni][r] = 0.f;

    {
        unsigned ah[8], bh[16];
        #pragma unroll
        for (int i = 0; i < 4; i++) {
            float4 v = *(const float4*)(Aptr + i * 4);
            ah[2 * i]     = f2h2(v.x, v.y);
            ah[2 * i + 1] = f2h2(v.z, v.w);
        }
        #pragma unroll
        for (int j = 0; j < 16; j++)
            bh[j] = f2h2(Bptr[(long long)(2 * j) * ldb], Bptr[(long long)(2 * j + 1) * ldb]);
        *(uint4*)(&As[0][a_r][a_kh])     = make_uint4(ah[0], ah[1], ah[2], ah[3]);
        *(uint4*)(&As[0][a_r][a_kh + 8]) = make_uint4(ah[4], ah[5], ah[6], ah[7]);
        *(uint4*)(&Bs[0][tid][0])  = make_uint4(bh[0],  bh[1],  bh[2],  bh[3]);
        *(uint4*)(&Bs[0][tid][8])  = make_uint4(bh[4],  bh[5],  bh[6],  bh[7]);
        *(uint4*)(&Bs[0][tid][16]) = make_uint4(bh[8],  bh[9],  bh[10], bh[11]);
        *(uint4*)(&Bs[0][tid][24]) = make_uint4(bh[12], bh[13], bh[14], bh[15]);
    }
    __syncthreads();

    const int nk = K >> 5;
    for (int t = 0; t < nk; t++) {
        const int buf = t & 1;
        unsigned ah[8], bh[16];
        if (t + 1 < nk) {
            int k0 = (t + 1) << 5;
            #pragma unroll
            for (int i = 0; i < 4; i++) {
                float4 v = *(const float4*)(Aptr + k0 + i * 4);
                ah[2 * i]     = f2h2(v.x, v.y);
                ah[2 * i + 1] = f2h2(v.z, v.w);
            }
            #pragma unroll
            for (int j = 0; j < 16; j++)
                bh[j] = f2h2(Bptr[(long long)(k0 + 2 * j) * ldb],
                             Bptr[(long long)(k0 + 2 * j + 1) * ldb]);
        }

        #pragma unroll
        for (int ks = 0; ks < 2; ks++) {
            unsigned ko = (unsigned)(ks * 32);
            unsigned ao = (unsigned)(buf * A2BUF) + ko;
            unsigned bo = (unsigned)(buf * B2BUF) + ko;
            unsigned af0[4], af1[4], bf[4][4];
            LDSM4(af0[0], af0[1], af0[2], af0[3], aaddr + ao);
            LDSM4(af1[0], af1[1], af1[2], af1[3], aaddr + 16u * ROWB + ao);
            #pragma unroll
            for (int j = 0; j < 4; j++)
                LDSM4(bf[j][0], bf[j][1], bf[j][2], bf[j][3], baddr[j] + bo);
            #pragma unroll
            for (int j = 0; j < 4; j++) {
                mma16816(acc[0][2 * j],     af0, &bf[j][0]);
                mma16816(acc[0][2 * j + 1], af0, &bf[j][2]);
                mma16816(acc[1][2 * j],     af1, &bf[j][0]);
                mma16816(acc[1][2 * j + 1], af1, &bf[j][2]);
            }
        }

        if (t + 1 < nk) {
            const int nb = (t + 1) & 1;
            *(uint4*)(&As[nb][a_r][a_kh])     = make_uint4(ah[0], ah[1], ah[2], ah[3]);
            *(uint4*)(&As[nb][a_r][a_kh + 8]) = make_uint4(ah[4], ah[5], ah[6], ah[7]);
            *(uint4*)(&Bs[nb][tid][0])  = make_uint4(bh[0],  bh[1],  bh[2],  bh[3]);
            *(uint4*)(&Bs[nb][tid][8])  = make_uint4(bh[4],  bh[5],  bh[6],  bh[7]);
            *(uint4*)(&Bs[nb][tid][16]) = make_uint4(bh[8],  bh[9],  bh[10], bh[11]);
            *(uint4*)(&Bs[nb][tid][24]) = make_uint4(bh[12], bh[13], bh[14], bh[15]);
            __syncthreads();
        }
    }

    #pragma unroll
    for (int mi = 0; mi < 2; mi++)
        #pragma unroll
        for (int ni = 0; ni < 8; ni++) {
            int r = row0 + wm + mi * 16 + g;
            int c = col0 + wn + ni * 8 + 2 * t4;
            float b0v = 0.f, b1v = 0.f;
            if (bias) { b0v = bias[c]; b1v = bias[c + 1]; }
            float o0 = acc[mi][ni][0] + b0v;
            float o1 = acc[mi][ni][1] + b1v;
            float o2 = acc[mi][ni][2] + b0v;
            float o3 = acc[mi][ni][3] + b1v;
            if (relu) {
                o0 = fmaxf(o0, 0.f); o1 = fmaxf(o1, 0.f);
                o2 = fmaxf(o2, 0.f); o3 = fmaxf(o3, 0.f);
            }
            *(float2*)(C + (long long)r * ldc + c)       = make_float2(o0, o1);
            *(float2*)(C + (long long)(r + 8) * ldc + c) = make_float2(o2, o3);
        }
}

// ======== NT GEMM fp16 (final bilinear): block 64x128, BK=32 ===============
__global__ __launch_bounds__(128) void mma_nt2h(
    const float* __restrict__ A, const float* __restrict__ B,
    float* __restrict__ C,
    int K, int lda, int ldb, int ldc,
    int zdiv, long long sA1, long long sA2, long long sB1, long long sB2,
    long long sC1, long long sC2, float scale)
{
    int z = blockIdx.z;
    int z1 = z / zdiv, z2 = z - z1 * zdiv;
    A += z1 * sA1 + (long long)z2 * sA2;
    B += z1 * sB1 + (long long)z2 * sB2;
    C += z1 * sC1 + (long long)z2 * sC2;

    __shared__ __align__(16) __half As[2][64][SH];
    __shared__ __align__(16) __half Bs[2][128][SH];

    const int tid = threadIdx.x;
    const int wid = tid >> 5, lane = tid & 31;
    const int wm = (wid >> 1) * 32, wn = (wid & 1) * 64;
    const int g = lane >> 2, t4 = lane & 3;
    const int row0 = blockIdx.y * 64, col0 = blockIdx.x * 128;

    const int a_r = tid >> 1, a_kh = (tid & 1) * 16;
    const float* Aptr = A + (long long)(row0 + a_r) * lda + a_kh;
    const float* Bptr = B + (long long)(col0 + tid) * ldb;

    const int lr = lane & 7, sel = lane >> 3;
    unsigned as0 = (unsigned)__cvta_generic_to_shared(&As[0][0][0]);
    unsigned bs0 = (unsigned)__cvta_generic_to_shared(&Bs[0][0][0]);
    unsigned aaddr = as0 + (unsigned)((wm + (sel & 1) * 8 + lr) * ROWB + (sel >> 1) * 16);
    unsigned baddr[4];
    #pragma unroll
    for (int j = 0; j < 4; j++)
        baddr[j] = bs0 + (unsigned)((wn + j * 16 + (sel >> 1) * 8 + lr) * ROWB + (sel & 1) * 16);

    float acc[2][8][4];
    #pragma unroll
    for (int mi = 0; mi < 2; mi++)
        #pragma unroll
        for (int ni = 0; ni < 8; ni++)
            #pragma unroll
            for (int r = 0; r < 4; r++) acc[mi][ni][r] = 0.f;

    {
        unsigned ah[8], bh[16];
        #pragma unroll
        for (int i = 0; i < 4; i++) {
            float4 v = *(const float4*)(Aptr + i * 4);
            ah[2 * i]     = f2h2(v.x, v.y);
            ah[2 * i + 1] = f2h2(v.z, v.w);
        }
        #pragma unroll
        for (int i = 0; i < 8; i++) {
            float4 v = *(const float4*)(Bptr + i * 4);
            bh[2 * i]     = f2h2(v.x, v.y);
            bh[2 * i + 1] = f2h2(v.z, v.w);
        }
        *(uint4*)(&As[0][a_r][a_kh])     = make_uint4(ah[0], ah[1], ah[2], ah[3]);
        *(uint4*)(&As[0][a_r][a_kh + 8]) = make_uint4(ah[4], ah[5], ah[6], ah[7]);
        *(uint4*)(&Bs[0][tid][0])  = make_uint4(bh[0],  bh[1],  bh[2],  bh[3]);
        *(uint4*)(&Bs[0][tid][8])  = make_uint4(bh[4],  bh[5],  bh[6],  bh[7]);
        *(uint4*)(&Bs[0][tid][16]) = make_uint4(bh[8],  bh[9],  bh[10], bh[11]);
        *(uint4*)(&Bs[0][tid][24]) = make_uint4(bh[12], bh[13], bh[14], bh[15]);
    }
    __syncthreads();

    const int nk = K >> 5;
    for (int t = 0; t < nk; t++) {
        const int buf = t & 1;
        unsigned ah[8], bh[16];
        if (t + 1 < nk) {
            int k0 = (t + 1) << 5;
            #pragma unroll
            for (int i = 0; i < 4; i++) {
                float4 v = *(const float4*)(Aptr + k0 + i * 4);
                ah[2 * i]     = f2h2(v.x, v.y);
                ah[2 * i + 1] = f2h2(v.z, v.w);
            }
            #pragma unroll
            for (int i = 0; i < 8; i++) {
                float4 v = *(const float4*)(Bptr + k0 + i * 4);
                bh[2 * i]     = f2h2(v.x, v.y);
                bh[2 * i + 1] = f2h2(v.z, v.w);
            }
        }

        #pragma unroll
        for (int ks = 0; ks < 2; ks++) {
            unsigned ko = (unsigned)(ks * 32);
            unsigned ao = (unsigned)(buf * A2BUF) + ko;
            unsigned bo = (unsigned)(buf * B2BUF) + ko;
            unsigned af0[4], af1[4], bf[4][4];
            LDSM4(af0[0], af0[1], af0[2], af0[3], aaddr + ao);
            LDSM4(af1[0], af1[1], af1[2], af1[3], aaddr + 16u * ROWB + ao);
            #pragma unroll
            for (int j = 0; j < 4; j++)
                LDSM4(bf[j][0], bf[j][1], bf[j][2], bf[j][3], baddr[j] + bo);
            #pragma unroll
            for (int j = 0; j < 4; j++) {
                mma16816(acc[0][2 * j],     af0, &bf[j][0]);
                mma16816(acc[0][2 * j + 1], af0, &bf[j][2]);
                mma16816(acc[1][2 * j],     af1, &bf[j][0]);
                mma16816(acc[1][2 * j + 1], af1, &bf[j][2]);
            }
        }

        if (t + 1 < nk) {
            const int nb = (t + 1) & 1;
            *(uint4*)(&As[nb][a_r][a_kh])     = make_uint4(ah[0], ah[1], ah[2], ah[3]);
            *(uint4*)(&As[nb][a_r][a_kh + 8]) = make_uint4(ah[4], ah[5], ah[6], ah[7]);
            *(uint4*)(&Bs[nb][tid][0])  = make_uint4(bh[0],  bh[1],  bh[2],  bh[3]);
            *(uint4*)(&Bs[nb][tid][8])  = make_uint4(bh[4],  bh[5],  bh[6],  bh[7]);
            *(uint4*)(&Bs[nb][tid][16]) = make_uint4(bh[8],  bh[9],  bh[10], bh[11]);
            *(uint4*)(&Bs[nb][tid][24]) = make_uint4(bh[12], bh[13], bh[14], bh[15]);
            __syncthreads();
        }
    }

    #pragma unroll
    for (int mi = 0; mi < 2; mi++)
        #pragma unroll
        for (int ni = 0; ni < 8; ni++) {
            int r = row0 + wm + mi * 16 + g;
            int c = col0 + wn + ni * 8 + 2 * t4;
            *(float2*)(C + (long long)r * ldc + c) =
                make_float2(acc[mi][ni][0] * scale, acc[mi][ni][1] * scale);
            *(float2*)(C + (long long)(r + 8) * ldc + c) =
                make_float2(acc[mi][ni][2] * scale, acc[mi][ni][3] * scale);
        }
}

// ======== fused flash attention (online softmax, static smem) ==============
// grid (NS/64, B*H), 128 threads. Q tile 64 x 64; keys in 4 chunks of 128.
__global__ __launch_bounds__(128) void flash_attn(
    const float* __restrict__ Qg, const float* __restrict__ Kg,
    const float* __restrict__ Vg, const int* __restrict__ mask,
    float* __restrict__ Og)
{
    __shared__ __align__(16) __half Qs[64 * (FA_KSTRB / 2)];
    __shared__ __align__(16) char KVraw[128 * FA_KSTRB];   // K chunk / Vt chunk
    __shared__ float msk[NS];

    const int bh = blockIdx.y;
    const int b = bh >> 3, h = bh & 7;
    const int q0 = blockIdx.x * 64;
    const float* Qp = Qg + (long long)b * NS * DM + h * DHH;
    const float* Kp = Kg + (long long)b * NS * DM + h * DHH;
    const float* Vp = Vg + (long long)b * NS * DM + h * DHH;

    const int tid = threadIdx.x;
    const int wid = tid >> 5, lane = tid & 31;
    const int g = lane >> 2, t4 = lane & 3;
    const int lr = lane & 7, sel = lane >> 3;

    unsigned qs_b = (unsigned)__cvta_generic_to_shared(Qs);
    unsigned kv_b = (unsigned)__cvta_generic_to_shared(KVraw);

    for (int j = tid; j < NS; j += 128)
        msk[j] = mask[b * NS + j] ? 0.f : -1e9f;

    // load Q tile: 2 threads per row, 32 floats each
    {
        int r = tid >> 1, kh = (tid & 1) * 32;
        const float* qp = Qp + (long long)(q0 + r) * DM + kh;
        __half* dst = Qs + r * (FA_KSTRB / 2) + kh;
        #pragma unroll
        for (int i = 0; i < 8; i++) {
            float4 v = *(const float4*)(qp + i * 4);
            *(uint2*)(dst + i * 4) = make_uint2(f2h2(v.x, v.y), f2h2(v.z, v.w));
        }
    }

    unsigned qa = qs_b + (unsigned)((wid * 16 + (sel & 1) * 8 + lr) * FA_KSTRB + (sel >> 1) * 16);

    float m0 = -1e30f, m1 = -1e30f, l0 = 0.f, l1 = 0.f;
    float o[8][4];
    #pragma unroll
    for (int p = 0; p < 8; p++)
        #pragma unroll
        for (int r = 0; r < 4; r++) o[p][r] = 0.f;

    for (int c = 0; c < 4; c++) {
        const int j0 = c * 128;
        // stage K chunk: thread -> key row j0+tid
        {
            const float* kp = Kp + (long long)(j0 + tid) * DM;
            __half* dst = (__half*)(KVraw + tid * FA_KSTRB);
            #pragma unroll
            for (int i = 0; i < 16; i++) {
                float4 v = *(const float4*)(kp + i * 4);
                *(uint2*)(dst + i * 4) = make_uint2(f2h2(v.x, v.y), f2h2(v.z, v.w));
            }
        }
        __syncthreads();

        // S = Q K^T for this chunk
        float s[16][4];
        #pragma unroll
        for (int p = 0; p < 16; p++)
            #pragma unroll
            for (int r = 0; r < 4; r++) s[p][r] = 0.f;

        #pragma unroll
        for (int ks = 0; ks < 4; ks++) {
            unsigned af[4];
            LDSM4(af[0], af[1], af[2], af[3], qa + ks * 32);
            #pragma unroll
            for (int p = 0; p < 8; p++) {
                unsigned bf[4];
                unsigned ba = kv_b + (unsigned)((p * 16 + (sel >> 1) * 8 + lr) * FA_KSTRB
                                                + (sel & 1) * 16) + ks * 32;
                LDSM4(bf[0], bf[1], bf[2], bf[3], ba);
                mma16816(s[2 * p],     af, &bf[0]);
                mma16816(s[2 * p + 1], af, &bf[2]);
            }
        }

        // mask + scale, per-row chunk max
        float cm0 = -1e30f, cm1 = -1e30f;
        #pragma unroll
        for (int p = 0; p < 16; p++) {
            int col = j0 + p * 8 + 2 * t4;
            float mv0 = msk[col], mv1 = msk[col + 1];
            s[p][0] = s[p][0] * 0.125f + mv0;
            s[p][1] = s[p][1] * 0.125f + mv1;
            s[p][2] = s[p][2] * 0.125f + mv0;
            s[p][3] = s[p][3] * 0.125f + mv1;
            cm0 = fmaxf(cm0, fmaxf(s[p][0], s[p][1]));
            cm1 = fmaxf(cm1, fmaxf(s[p][2], s[p][3]));
        }
        cm0 = fmaxf(cm0, __shfl_xor_sync(0xffffffffu, cm0, 1));
        cm0 = fmaxf(cm0, __shfl_xor_sync(0xffffffffu, cm0, 2));
        cm1 = fmaxf(cm1, __shfl_xor_sync(0xffffffffu, cm1, 1));
        cm1 = fmaxf(cm1, __shfl_xor_sync(0xffffffffu, cm1, 2));

        float nm0 = fmaxf(m0, cm0), nm1 = fmaxf(m1, cm1);
        float sc0 = __expf(m0 - nm0), sc1 = __expf(m1 - nm1);
        m0 = nm0; m1 = nm1;
        l0 *= sc0; l1 *= sc1;
        #pragma unroll
        for (int p = 0; p < 8; p++) {
            o[p][0] *= sc0; o[p][1] *= sc0;
            o[p][2] *= sc1; o[p][3] *= sc1;
        }

        // P = exp(S - m), accumulate partial row sums
        #pragma unroll
        for (int p = 0; p < 16; p++) {
            s[p][0] = __expf(s[p][0] - m0);
            s[p][1] = __expf(s[p][1] - m0);
            s[p][2] = __expf(s[p][2] - m1);
            s[p][3] = __expf(s[p][3] - m1);
            l0 += s[p][0] + s[p][1];
            l1 += s[p][2] + s[p][3];
        }
        __syncthreads();   // done reading K chunk

        // stage V chunk transposed: Vt[dh 64][key 128], row stride FA_VSTRB
        {
            const float* vp = Vp + (long long)(j0 + tid) * DM;
            __half* base = (__half*)KVraw + tid;    // key column tid
            #pragma unroll
            for (int i = 0; i < 16; i++) {
                float4 v = *(const float4*)(vp + i * 4);
                base[(4 * i + 0) * (FA_VSTRB / 2)] = __float2half_rn(v.x);
                base[(4 * i + 1) * (FA_VSTRB / 2)] = __float2half_rn(v.y);
                base[(4 * i + 2) * (FA_VSTRB / 2)] = __float2half_rn(v.z);
                base[(4 * i + 3) * (FA_VSTRB / 2)] = __float2half_rn(v.w);
            }
        }
        __syncthreads();

        // O += P @ V   (A fragments repacked directly from s registers)
        #pragma unroll
        for (int p = 0; p < 8; p++) {     // k-steps of 16 keys
            unsigned af[4];
            af[0] = f2h2(s[2 * p][0],     s[2 * p][1]);
            af[1] = f2h2(s[2 * p][2],     s[2 * p][3]);
            af[2] = f2h2(s[2 * p + 1][0], s[2 * p + 1][1]);
            af[3] = f2h2(s[2 * p + 1][2], s[2 * p + 1][3]);
            #pragma unroll
            for (int n = 0; n < 4; n++) {
                unsigned bf[4];
                unsigned ba = kv_b + (unsigned)((n * 16 + (sel >> 1) * 8 + lr) * FA_VSTRB
                                                + ((sel & 1) * 8 + p * 16) * 2);
                LDSM4(bf[0], bf[1], bf[2], bf[3], ba);
                mma16816(o[2 * n],     af, &bf[0]);
                mma16816(o[2 * n + 1], af, &bf[2]);
            }
        }
        __syncthreads();   // done reading V before next chunk's K store
    }

    l0 += __shfl_xor_sync(0xffffffffu, l0, 1);
    l0 += __shfl_xor_sync(0xffffffffu, l0, 2);
    l1 += __shfl_xor_sync(0xffffffffu, l1, 1);
    l1 += __shfl_xor_sync(0xffffffffu, l1, 2);
    const float inv0 = 1.f / l0, inv1 = 1.f / l1;

    {
        int r0 = q0 + wid * 16 + g;
        float* out0 = Og + ((long long)b * NS + r0) * DM + h * DHH;
        float* out1 = out0 + 8ll * DM;
        #pragma unroll
        for (int p = 0; p < 8; p++) {
            int cc = p * 8 + 2 * t4;
            *(float2*)(out0 + cc) = make_float2(o[p][0] * inv0, o[p][1] * inv0);
            *(float2*)(out1 + cc) = make_float2(o[p][2] * inv1, o[p][3] * inv1);
        }
    }
}

// out[row] = LN(x[row] + y[row]) * g + b.
__global__ __launch_bounds__(256) void ln_add(
    const float* __restrict__ X, const float* __restrict__ Y,
    const float* __restrict__ g, const float* __restrict__ be,
    float* __restrict__ O)
{
    int row = blockIdx.x;
    const float* xp = X + (long long)row * DM;
    const float* yp = Y + (long long)row * DM;
    float* op = O + (long long)row * DM;
    int tid = threadIdx.x;

    float a0 = xp[tid] + yp[tid];
    float a1 = xp[tid + 256] + yp[tid + 256];

    __shared__ float r1[256];
    __shared__ float r2[256];
    r1[tid] = a0 + a1;
    r2[tid] = a0 * a0 + a1 * a1;
    __syncthreads();
    for (int s = 128; s > 0; s >>= 1) {
        if (tid < s) { r1[tid] += r1[tid + s]; r2[tid] += r2[tid + s]; }
        __syncthreads();
    }
    float mean = r1[0] * (1.f / DM);
    float var  = r2[0] * (1.f / DM) - mean * mean;
    float rstd = rsqrtf(var + LN_EPS);
    op[tid]       = (a0 - mean) * rstd * g[tid]       + be[tid];
    op[tid + 256] = (a1 - mean) * rstd * g[tid + 256] + be[tid + 256];
}

__global__ void vmul_k(const float* __restrict__ v, const float* __restrict__ w,
                       float* __restrict__ o, int n) {
    int i = blockIdx.x * blockDim.x + threadIdx.x;
    if (i < n) o[i] = v[i] * w[i & (DM - 1)];
}

__global__ __launch_bounds__(256) void softmax_final(
    float* __restrict__ S, const int* __restrict__ vmask,
    const int* __restrict__ qmask, const float* __restrict__ attb)
{
    int row = blockIdx.x;
    int b = row >> 9, i = row & (NS - 1);
    int rowpad = (vmask[b * NS + i] == 0);
    float ab = attb[0];
    float* Sp = S + (long long)row * NS;
    int tid = threadIdx.x;

    float v0 = (rowpad || qmask[b * NS + tid] == 0)       ? -1e9f : Sp[tid] + ab;
    float v1 = (rowpad || qmask[b * NS + tid + 256] == 0) ? -1e9f : Sp[tid + 256] + ab;

    __shared__ float red[256];
    red[tid] = fmaxf(v0, v1);
    __syncthreads();
    for (int s = 128; s > 0; s >>= 1) {
        if (tid < s) red[tid] = fmaxf(red[tid], red[tid + s]);
        __syncthreads();
    }
    float m = red[0];
    __syncthreads();

    float e0 = __expf(v0 - m), e1 = __expf(v1 - m);
    red[tid] = e0 + e1;
    __syncthreads();
    for (int s = 128; s > 0; s >>= 1) {
        if (tid < s) red[tid] += red[tid + s];
        __syncthreads();
    }
    float inv = 1.f / red[0];
    Sp[tid]       = e0 * inv;
    Sp[tid + 256] = e1 * inv;
}

__global__ void final_out_k(const float* __restrict__ V, const float* __restrict__ T,
                            float* __restrict__ out) {
    int b = blockIdx.x;
    int k = threadIdx.x;
    const float* vp = V + (long long)b * NS * DM;
    const float* tp = T + (long long)b * NS * DM;
    float acc = 0.f;
    #pragma unroll 4
    for (int i = 0; i < NS; i++)
        acc = fmaf(vp[(long long)i * DM + k], tp[(long long)i * DM + k], acc);
    out[b * DM + k] = acc * (1.f / 512.f);
}

// ------------------------------- host side ---------------------------------

static void run_mha(const float* xq, const float* xkv, const int* mask,
                    const float* w, const float* b,
                    const float* wo, const float* bo,
                    float* QKV, float* AO, float* out)
{
    const long long NT = (long long)BB * NS * DM;
    const long long WSTRIDE = (long long)DM * DM;
    const dim3 gP(DM / 128, (BB * NS) / 64, 1);

    if (xq == xkv) {
        mma_nn2h<<<dim3(DM / 128, (BB * NS) / 64, 3), 128>>>(
            xq, w, b, QKV, DM, DM, DM, DM,
            3, 0, 0, 0, WSTRIDE, 0, NT, DM, 0);
    } else {
        mma_nn2h<<<gP, 128>>>(
            xq, w, b, QKV, DM, DM, DM, DM,
            1, 0, 0, 0, 0, 0, 0, DM, 0);
        mma_nn2h<<<dim3(DM / 128, (BB * NS) / 64, 2), 128>>>(
            xkv, w + WSTRIDE, b + DM, QKV + NT, DM, DM, DM, DM,
            2, 0, 0, 0, WSTRIDE, 0, NT, DM, 0);
    }

    flash_attn<<<dim3(NS / 64, BB * NHEAD), 128>>>(
        QKV, QKV + NT, QKV + 2 * NT, mask, AO);

    mma_nn2h<<<gP, 128>>>(
        AO, wo, bo, out, DM, DM, DM, DM,
        1, 0, 0, 0, 0, 0, 0, DM, 0);
}

extern "C" void kernel_launch(void* const* d_in, const int* in_sizes, int n_in,
                              void* d_out, int out_size)
{
    const float *v_in, *q_in, *attn_w, *attn_b, *attn_wo, *attn_bo;
    const float *ln_g, *ln_b, *fw1, *fb1, *fw2, *fb2, *att_w, *att_b;
    const int *v_mask, *q_mask;

    if (in_sizes[2] == BB * NS) {   // dict order
        v_in    = (const float*)d_in[0];
        q_in    = (const float*)d_in[1];
        v_mask  = (const int*)  d_in[2];
        q_mask  = (const int*)  d_in[3];
        attn_w  = (const float*)d_in[4];
        attn_b  = (const float*)d_in[5];
        attn_wo = (const float*)d_in[6];
        attn_bo = (const float*)d_in[7];
        ln_g    = (const float*)d_in[8];
        ln_b    = (const float*)d_in[9];
        fw1     = (const float*)d_in[10];
        fb1     = (const float*)d_in[11];
        fw2     = (const float*)d_in[12];
        fb2     = (const float*)d_in[13];
        att_w   = (const float*)d_in[14];
        att_b   = (const float*)d_in[15];
    } else {                        // signature order
        v_in    = (const float*)d_in[0];
        q_in    = (const float*)d_in[1];
        attn_w  = (const float*)d_in[2];
        attn_b  = (const float*)d_in[3];
        attn_wo = (const float*)d_in[4];
        attn_bo = (const float*)d_in[5];
        ln_g    = (const float*)d_in[6];
        ln_b    = (const float*)d_in[7];
        fw1     = (const float*)d_in[8];
        fb1     = (const float*)d_in[9];
        fw2     = (const float*)d_in[10];
        fb2     = (const float*)d_in[11];
        att_w   = (const float*)d_in[12];
        att_b   = (const float*)d_in[13];
        v_mask  = (const int*)  d_in[14];
        q_mask  = (const int*)  d_in[15];
    }

    float *V, *Q, *QKV, *SC, *AO, *TMP, *VA, *QA, *VQ, *QV, *FFN;
    cudaGetSymbolAddress((void**)&V,   g_v);
    cudaGetSymbolAddress((void**)&Q,   g_q);
    cudaGetSymbolAddress((void**)&QKV, g_qkv);
    cudaGetSymbolAddress((void**)&SC,  g_sc);
    cudaGetSymbolAddress((void**)&AO,  g_ao);
    cudaGetSymbolAddress((void**)&TMP, g_tmp);
    cudaGetSymbolAddress((void**)&VA,  g_va);
    cudaGetSymbolAddress((void**)&QA,  g_qa);
    cudaGetSymbolAddress((void**)&VQ,  g_vq);
    cudaGetSymbolAddress((void**)&QV,  g_qv);
    cudaGetSymbolAddress((void**)&FFN, g_ffn);

    const int NTOK = BB * NS * DM;
    const long long NT = (long long)NTOK;
    const long long SBATCH = (long long)NS * DM;
    copy_k<<<(NTOK + 255) / 256, 256>>>(v_in, V, NTOK);
    copy_k<<<(NTOK + 255) / 256, 256>>>(q_in, Q, NTOK);

    const int rows = BB * NS;

    for (int i = 0; i < NLAY; i++) {
        const float* aw  = attn_w  + (long long)i * 4 * 3 * DM * DM;
        const float* ab  = attn_b  + (long long)i * 4 * 3 * DM;
        const float* awo = attn_wo + (long long)i * 4 * DM * DM;
        const float* abo = attn_bo + (long long)i * 4 * DM;
        const float* lg  = ln_g + (long long)i * 6 * DM;
        const float* lb  = ln_b + (long long)i * 6 * DM;

        run_mha(V, V, v_mask, aw, ab, awo, abo, QKV, AO, TMP);
        ln_add<<<rows, 256>>>(V, TMP, lg, lb, VA);

        run_mha(Q, Q, q_mask,
                aw + 3ll * DM * DM, ab + 3 * DM, awo + (long long)DM * DM, abo + DM,
                QKV, AO, TMP);
        ln_add<<<rows, 256>>>(Q, TMP, lg + DM, lb + DM, QA);

        run_mha(VA, QA, q_mask,
                aw + 6ll * DM * DM, ab + 6 * DM, awo + 2ll * DM * DM, abo + 2 * DM,
                QKV, AO, VQ);
        run_mha(QA, VQ, v_mask,
                aw + 9ll * DM * DM, ab + 9 * DM, awo + 3ll * DM * DM, abo + 3 * DM,
                QKV, AO, QV);

        ln_add<<<rows, 256>>>(V, VQ, lg + 2 * DM, lb + 2 * DM, V);
        ln_add<<<rows, 256>>>(Q, QV, lg + 3 * DM, lb + 3 * DM, Q);

        const float* w1v = fw1 + (long long)i * 2 * DM * DFF;
        const float* b1v = fb1 + (long long)i * 2 * DFF;
        const float* w2v = fw2 + (long long)i * 2 * DFF * DM;
        const float* b2v = fb2 + (long long)i * 2 * DM;

        mma_nn2h<<<dim3(DFF / 128, rows / 64, 1), 128>>>(
            V, w1v, b1v, FFN, DM, DM, DFF, DFF,
            1, 0, 0, 0, 0, 0, 0, 0, 1);
        mma_nn2h<<<dim3(DM / 128, rows / 64, 1), 128>>>(
            FFN, w2v, b2v, TMP, DFF, DFF, DM, DM,
            1, 0, 0, 0, 0, 0, 0, 0, 0);
        ln_add<<<rows, 256>>>(V, TMP, lg + 4 * DM, lb + 4 * DM, V);

        mma_nn2h<<<dim3(DFF / 128, rows / 64, 1), 128>>>(
            Q, w1v + (long long)DM * DFF, b1v + DFF, FFN, DM, DM, DFF, DFF,
            1, 0, 0, 0, 0, 0, 0, 0, 1);
        mma_nn2h<<<dim3(DM / 128, rows / 64, 1), 128>>>(
            FFN, w2v + (long long)DFF * DM, b2v + DM, TMP, DFF, DFF, DM, DM,
            1, 0, 0, 0, 0, 0, 0, 0, 0);
        ln_add<<<rows, 256>>>(Q, TMP, lg + 5 * DM, lb + 5 * DM, Q);
    }

    // Final bilinear attention pooling.
    float* PQs = QKV;
    float* Ts  = QKV + NT;
    vmul_k<<<(NTOK + 255) / 256, 256>>>(V, att_w, PQs, NTOK);
    mma_nt2h<<<dim3(NS / 128, NS / 64, BB), 128>>>(
        PQs, Q, SC, DM, DM, DM, NS,
        1, SBATCH, 0, SBATCH, 0, (long long)NS * NS, 0, 1.0f);
    softmax_final<<<BB * NS, 256>>>(SC, v_mask, q_mask, att_b);
    mma_nn2h<<<dim3(DM / 128, NS / 64, BB), 128>>>(
        SC, Q, (const float*)nullptr, Ts, NS, NS, DM, DM,
        1, (long long)NS * NS, 0, SBATCH, 0, SBATCH, 0, 0, 0);
    final_out_k<<<BB, 512>>>(V, Ts, (float*)d_out);
}